// round 14
// baseline (speedup 1.0000x reference)
#include <cuda_runtime.h>
#include <cuda_fp16.h>
#include <cstdint>

// ---------------------------------------------------------------------------
// Decoder: emb gather + concat -> fused [wavefront LSTM x2 + FC drain]
// B=64, T=32, E=H=512, V=32000.  Round-10 base (best measured) plus:
//  (1) projection GEMM = R7/R8 BN=256 config (proven);
//  (2) wave staging via cp.async with reordered waits (hsfB copy overlaps
//      the flags1 wait); no other changes.
// ---------------------------------------------------------------------------
#define B_  64
#define T_  32
#define E_  512
#define H_  512
#define V_  32000
#define M_  (B_ * T_)    // 2048
#define G4_ (4 * H_)     // 2048
#define NFCT 2000        // FC tiles: 4 tgroups x 4 btiles x 125 ntiles (N=256)

__device__ __half   g_x0[M_ * E_];
__device__ float    g_xp[M_ * G4_];
__device__ __half   g_hseq[M_ * H_];
__device__ __half   g_wih0[G4_ * E_];
__device__ __half   g_wih1[G4_ * H_];
__device__ __half   g_fcw[V_ * H_];
__device__ __align__(16) __half g_h1ring[4][B_ * H_];
__device__ __align__(16) __half g_h2f[2][B_ * H_];
__device__ unsigned g_flags1[64 * 4];
__device__ unsigned g_flags2[64 * 4];
__device__ unsigned g_ticket;

// ---------------------------------------------------------------------------
__device__ __forceinline__ uint32_t packh2(float a, float b) {
    __half2 h = __floats2half2_rn(a, b);
    return *(uint32_t*)&h;
}

__device__ __forceinline__ void mma_f16(float (&c)[4], const uint32_t (&a)[4],
                                        const uint32_t (&b)[2]) {
    asm volatile(
        "mma.sync.aligned.m16n8k16.row.col.f32.f16.f16.f32 "
        "{%0,%1,%2,%3}, {%4,%5,%6,%7}, {%8,%9}, {%0,%1,%2,%3};\n"
        : "+f"(c[0]), "+f"(c[1]), "+f"(c[2]), "+f"(c[3])
        : "r"(a[0]), "r"(a[1]), "r"(a[2]), "r"(a[3]), "r"(b[0]), "r"(b[1]));
}

__device__ __forceinline__ void st_rel(unsigned* p, unsigned v) {
    asm volatile("st.release.gpu.global.u32 [%0], %1;" :: "l"(p), "r"(v)
                 : "memory");
}
__device__ __forceinline__ unsigned ld_acq(unsigned* p) {
    unsigned v;
    asm volatile("ld.acquire.gpu.global.u32 %0, [%1];" : "=r"(v) : "l"(p)
                 : "memory");
    return v;
}

__device__ __forceinline__ uint32_t smem_u32(const void* p) {
    uint32_t a;
    asm("{ .reg .u64 t; cvta.to.shared.u64 t, %1; cvt.u32.u64 %0, t; }"
        : "=r"(a) : "l"(p));
    return a;
}

__device__ __forceinline__ void cp16(uint32_t dst, const void* src) {
    asm volatile("cp.async.cg.shared.global [%0], [%1], 16;\n"
                 :: "r"(dst), "l"(src));
}

// m16n8k16 A-fragment-layout store (h ring buffers)
__device__ __forceinline__ void st_hfrag(__half* base, int b, int j, __half h) {
    int mt     = b >> 4;
    int kt     = j >> 4;
    int lane_t = (b & 7) * 4 + ((j >> 1) & 3);
    int q      = ((b >> 3) & 1) | (((j >> 3) & 1) << 1);
    base[(((mt * 32 + kt) * 32 + lane_t) << 3) + (q << 1) + (j & 1)] = h;
}

// ---------------------------------------------------------------------------
__global__ void to_half(const float* __restrict__ src, __half* __restrict__ dst,
                        int n4) {
    int i = blockIdx.x * blockDim.x + threadIdx.x;
    if (i >= n4) return;
    float4 v = *(const float4*)(src + (size_t)i * 4);
    uint2 u;
    u.x = packh2(v.x, v.y);
    u.y = packh2(v.z, v.w);
    *(uint2*)(dst + (size_t)i * 4) = u;
}

__global__ void build_x0(const int* __restrict__ sentence,
                         const float* __restrict__ features,
                         const float* __restrict__ emb,
                         __half* __restrict__ x0) {
    int i4 = blockIdx.x * blockDim.x + threadIdx.x;
    if (i4 >= M_ * (E_ / 4)) return;
    int m  = i4 >> 7;
    int e4 = (i4 & 127) * 4;
    int b  = m >> 5;
    int t  = m & 31;
    float4 v;
    if (t == 0) {
        v = *(const float4*)&features[b * E_ + e4];
    } else {
        int tok = sentence[b * T_ + (t - 1)];
        v = *(const float4*)&emb[tok * E_ + e4];
    }
    uint2 u;
    u.x = packh2(v.x, v.y);
    u.y = packh2(v.z, v.w);
    *(uint2*)(x0 + (size_t)m * E_ + e4) = u;
}

__global__ void reset_bar() {
    int i = threadIdx.x;
    if (i < 256) { g_flags1[i] = 0; g_flags2[i] = 0; }
    if (i == 0) g_ticket = 0;
}

// ---------------------------------------------------------------------------
// Projection GEMM (R7/R8 proven): BM=128 BN=256 BK=32, 4-stage cp.async,
// 8 warps (2m x 4n), warp tile 64x64, K=512, row-major C + bias1 + bias2.
// ---------------------------------------------------------------------------
#define HLDW 20
#define GSTG ((128 + 256) * HLDW * 4)   // 30720 B/stage

__global__ void __launch_bounds__(256)
gemm_proj(const __half* __restrict__ A, const __half* __restrict__ Bm,
          const float* __restrict__ bias1, const float* __restrict__ bias2,
          float* __restrict__ C, int M, int N, int K) {
    extern __shared__ uint8_t dsm[];
    const uint32_t base = smem_u32(dsm);

    const int tid  = threadIdx.x;
    const int lane = tid & 31;
    const int warp = tid >> 5;
    const int wm = (warp & 1) * 64;
    const int wn = (warp >> 1) * 64;
    const int m0 = blockIdx.y * 128;
    const int n0 = blockIdx.x * 256;

    float acc[4][8][4];
#pragma unroll
    for (int mt = 0; mt < 4; mt++)
#pragma unroll
        for (int nt = 0; nt < 8; nt++)
#pragma unroll
            for (int i = 0; i < 4; i++) acc[mt][nt][i] = 0.f;

    auto issue = [&](int s) {
        uint32_t sa = base + (s & 3) * GSTG;
        uint32_t sb = sa + 128 * HLDW * 4;
        const __half* ap = A + (size_t)m0 * K + s * 32;
        const __half* wp = Bm + (size_t)n0 * K + s * 32;
#pragma unroll
        for (int i = 0; i < 2; i++) {
            int c = i * 256 + tid;
            int row = c >> 2, kk = c & 3;
            cp16(sa + (uint32_t)(row * 80 + kk * 16),
                 ap + (size_t)row * K + kk * 8);
        }
#pragma unroll
        for (int i = 0; i < 4; i++) {
            int c = i * 256 + tid;
            int row = c >> 2, kk = c & 3;
            cp16(sb + (uint32_t)(row * 80 + kk * 16),
                 wp + (size_t)row * K + kk * 8);
        }
    };

#pragma unroll
    for (int s = 0; s < 3; s++) {
        issue(s);
        asm volatile("cp.async.commit_group;" ::: "memory");
    }

    for (int k = 0; k < 16; k++) {
        if (k <= 13)      asm volatile("cp.async.wait_group 2;" ::: "memory");
        else if (k == 14) asm volatile("cp.async.wait_group 1;" ::: "memory");
        else              asm volatile("cp.async.wait_group 0;" ::: "memory");
        __syncthreads();
        if (k + 3 < 16) {
            issue(k + 3);
            asm volatile("cp.async.commit_group;" ::: "memory");
        }

        const uint32_t* As = (const uint32_t*)(dsm + (size_t)(k & 3) * GSTG);
        const uint32_t* Bs = As + 128 * HLDW;
#pragma unroll
        for (int ks = 0; ks < 2; ks++) {
            int kc = ks * 8 + (lane & 3);
            uint32_t bf[8][2];
#pragma unroll
            for (int nt = 0; nt < 8; nt++) {
                int nr = wn + nt * 8 + (lane >> 2);
                bf[nt][0] = Bs[nr * HLDW + kc];
                bf[nt][1] = Bs[nr * HLDW + kc + 4];
            }
#pragma unroll
            for (int mt = 0; mt < 4; mt++) {
                int r = wm + mt * 16 + (lane >> 2);
                uint32_t af[4];
                af[0] = As[r * HLDW + kc];
                af[1] = As[(r + 8) * HLDW + kc];
                af[2] = As[r * HLDW + kc + 4];
                af[3] = As[(r + 8) * HLDW + kc + 4];
#pragma unroll
                for (int nt = 0; nt < 8; nt++)
                    mma_f16(acc[mt][nt], af, bf[nt]);
            }
        }
    }

#pragma unroll
    for (int nt = 0; nt < 8; nt++) {
        int cn  = n0 + wn + nt * 8 + (lane & 3) * 2;
        float bv0 = bias1[cn] + bias2[cn];
        float bv1 = bias1[cn + 1] + bias2[cn + 1];
#pragma unroll
        for (int mt = 0; mt < 4; mt++) {
            int r = m0 + wm + mt * 16 + (lane >> 2);
            C[(size_t)r * N + cn]           = acc[mt][nt][0] + bv0;
            C[(size_t)r * N + cn + 1]       = acc[mt][nt][1] + bv1;
            C[(size_t)(r + 8) * N + cn]     = acc[mt][nt][2] + bv0;
            C[(size_t)(r + 8) * N + cn + 1] = acc[mt][nt][3] + bv1;
        }
    }
}

// ---------------------------------------------------------------------------
// Fused wave + FC kernel (round-10 structure). Grid 148 x 256, 192KB smem.
// Blocks 0-63: LSTM layer 1. Blocks 64-127: LSTM layer 2 (fused input proj).
// Blocks 128-147: FC workers. Wave blocks join FC pool after T_ steps.
// FC tile: M=128 (16b x 8t), N=256, K=512; gated on layer-2 progress.
// ---------------------------------------------------------------------------
#define FSTG ((128 + 256) * HLDW * 4)   // 30720 B/stage, x4 = 122880

__global__ void __launch_bounds__(256, 1)
wave_fc(const float* __restrict__ xp0, const float* __restrict__ Whh0,
        const __half* __restrict__ wih1, const float* __restrict__ Whh1,
        const float* __restrict__ bih1, const float* __restrict__ bhh1,
        __half* __restrict__ hseq,
        const __half* __restrict__ fcw, const float* __restrict__ fcb,
        float* __restrict__ out) {
    extern __shared__ uint32_t smu[];
    __shared__ int s_w;
    const int tid  = threadIdx.x;
    const int lane = tid & 31;
    const int w    = tid >> 5;
    const int gid  = lane >> 2;
    const int tig  = lane & 3;
    const int jj   = tid & 7;
    const int bq   = tid >> 3;
    float creg0 = 0.f, creg1 = 0.f;

    if (blockIdx.x < 64) {
        // ================= layer 1 =================
        uint32_t* hsf = smu;                    // 64KB
        float*    red = (float*)(smu + 16384);  // 64KB
        const int j0 = blockIdx.x * 8;
        const uint32_t hsfb = smem_u32(hsf);

        uint32_t bfr[4][4][2];
#pragma unroll
        for (int nt = 0; nt < 4; nt++)
#pragma unroll
            for (int ktl = 0; ktl < 4; ktl++) {
                int n  = nt * H_ + j0 + gid;
                int kb = w * 64 + ktl * 16 + tig * 2;
                const float* wr = Whh0 + (size_t)n * H_;
                bfr[nt][ktl][0] = packh2(wr[kb],     wr[kb + 1]);
                bfr[nt][ktl][1] = packh2(wr[kb + 8], wr[kb + 9]);
            }

#pragma unroll 4
        for (int i = tid; i < 4096; i += 256)
            ((uint4*)hsf)[i] = make_uint4(0u, 0u, 0u, 0u);

        for (int t = 0; t < T_; t++) {
            float xpr[2][4];
#pragma unroll
            for (int half = 0; half < 2; half++) {
                int b = bq + half * 32;
#pragma unroll
                for (int g = 0; g < 4; g++)
                    xpr[half][g] =
                        xp0[(size_t)(b * T_ + t) * G4_ + g * H_ + j0 + jj];
            }

            if (t > 0) {
                if (tid < 64) {
                    while (ld_acq(&g_flags1[tid * 4]) < (unsigned)t)
                        __nanosleep(64);
                } else if (tid < 128 && t >= 4) {
                    while (ld_acq(&g_flags2[(tid - 64) * 4]) < (unsigned)(t - 3))
                        __nanosleep(64);
                }
                __syncthreads();
                const uint8_t* src = (const uint8_t*)g_h1ring[(t - 1) & 3];
#pragma unroll
                for (int it = 0; it < 16; it++) {
                    int idx = it * 256 + tid;
                    cp16(hsfb + (uint32_t)idx * 16, src + (size_t)idx * 16);
                }
                asm volatile("cp.async.commit_group;" ::: "memory");
                asm volatile("cp.async.wait_group 0;" ::: "memory");
            }
            __syncthreads();

            float acc[4][4][4];
#pragma unroll
            for (int mt = 0; mt < 4; mt++)
#pragma unroll
                for (int nt = 0; nt < 4; nt++)
#pragma unroll
                    for (int i = 0; i < 4; i++) acc[mt][nt][i] = 0.f;

#pragma unroll
            for (int ktl = 0; ktl < 4; ktl++) {
                int kt = w * 4 + ktl;
#pragma unroll
                for (int mt = 0; mt < 4; mt++) {
                    uint4 av = *(const uint4*)&hsf[(((mt * 32 + kt) * 32) + lane) * 4];
                    uint32_t a[4] = {av.x, av.y, av.z, av.w};
#pragma unroll
                    for (int nt = 0; nt < 4; nt++)
                        mma_f16(acc[mt][nt], a, bfr[nt][ktl]);
                }
            }

#pragma unroll
            for (int mt = 0; mt < 4; mt++)
#pragma unroll
                for (int nt = 0; nt < 4; nt++)
                    *(float4*)&red[(((w * 4 + mt) * 4 + nt) << 7) + lane * 4] =
                        make_float4(acc[mt][nt][0], acc[mt][nt][1],
                                    acc[mt][nt][2], acc[mt][nt][3]);
            __syncthreads();

            __half* ring = g_h1ring[t & 3];
#pragma unroll
            for (int half = 0; half < 2; half++) {
                int b     = bq + half * 32;
                int row_t = b & 15;
                int mt    = b >> 4;
                int pos   = (((row_t & 7) * 4 + (jj >> 1)) << 2) + (jj & 1) +
                            ((row_t >> 3) << 1);
                float gv[4];
#pragma unroll
                for (int g = 0; g < 4; g++) {
                    float s = xpr[half][g];
#pragma unroll
                    for (int ww = 0; ww < 8; ww++)
                        s += red[(((ww * 4 + mt) * 4 + g) << 7) + pos];
                    gv[g] = s;
                }
                float ig = 1.f / (1.f + __expf(-gv[0]));
                float fg = 1.f / (1.f + __expf(-gv[1]));
                float gg = tanhf(gv[2]);
                float og = 1.f / (1.f + __expf(-gv[3]));
                float cold = half ? creg1 : creg0;
                float cn = fg * cold + ig * gg;
                if (half) creg1 = cn; else creg0 = cn;
                float hn = og * tanhf(cn);
                st_hfrag(ring, b, j0 + jj, __float2half_rn(hn));
            }

            __syncthreads();
            if (tid == 0) st_rel(&g_flags1[blockIdx.x * 4], (unsigned)(t + 1));
        }
    } else if (blockIdx.x < 128) {
        // ================= layer 2 (fused input projection) =================
        uint32_t* hsfA = smu;                    // 64KB h1
        uint32_t* hsfB = smu + 16384;            // 64KB h2
        float*    red  = (float*)(smu + 32768);  // 64KB
        const int bid2 = blockIdx.x - 64;
        const int j0 = bid2 * 8;
        const int wq = w & 3;
        const bool isH1 = (w < 4);
        const uint32_t hbA = smem_u32(hsfA);
        const uint32_t hbB = smem_u32(hsfB);

        uint32_t bfr[4][8][2];
#pragma unroll
        for (int nt = 0; nt < 4; nt++)
#pragma unroll
            for (int ktl = 0; ktl < 8; ktl++) {
                int n  = nt * H_ + j0 + gid;
                int kb = wq * 128 + ktl * 16 + tig * 2;
                if (isH1) {
                    bfr[nt][ktl][0] = *(const uint32_t*)&wih1[(size_t)n * H_ + kb];
                    bfr[nt][ktl][1] = *(const uint32_t*)&wih1[(size_t)n * H_ + kb + 8];
                } else {
                    const float* wr = Whh1 + (size_t)n * H_;
                    bfr[nt][ktl][0] = packh2(wr[kb],     wr[kb + 1]);
                    bfr[nt][ktl][1] = packh2(wr[kb + 8], wr[kb + 9]);
                }
            }

        float bs[4];
#pragma unroll
        for (int g = 0; g < 4; g++)
            bs[g] = bih1[g * H_ + j0 + jj] + bhh1[g * H_ + j0 + jj];

#pragma unroll 4
        for (int i = tid; i < 4096; i += 256)
            ((uint4*)hsfB)[i] = make_uint4(0u, 0u, 0u, 0u);

        for (int s = 0; s < T_; s++) {
            // (1) wait peers' h2[s-1]; stage hsfB async (overlaps flags1 wait)
            if (s > 0) {
                if (tid < 64) {
                    while (ld_acq(&g_flags2[tid * 4]) < (unsigned)s)
                        __nanosleep(64);
                }
                __syncthreads();
                const uint8_t* srcB = (const uint8_t*)g_h2f[(s - 1) & 1];
#pragma unroll
                for (int it = 0; it < 16; it++) {
                    int idx = it * 256 + tid;
                    cp16(hbB + (uint32_t)idx * 16, srcB + (size_t)idx * 16);
                }
                asm volatile("cp.async.commit_group;" ::: "memory");
            }
            // (2) wait h1[s]; stage hsfA async; drain both
            if (tid < 64) {
                while (ld_acq(&g_flags1[tid * 4]) < (unsigned)(s + 1))
                    __nanosleep(64);
            }
            __syncthreads();
            {
                const uint8_t* srcA = (const uint8_t*)g_h1ring[s & 3];
#pragma unroll
                for (int it = 0; it < 16; it++) {
                    int idx = it * 256 + tid;
                    cp16(hbA + (uint32_t)idx * 16, srcA + (size_t)idx * 16);
                }
                asm volatile("cp.async.commit_group;" ::: "memory");
                asm volatile("cp.async.wait_group 0;" ::: "memory");
            }
            __syncthreads();

            float acc[4][4][4];
#pragma unroll
            for (int mt = 0; mt < 4; mt++)
#pragma unroll
                for (int nt = 0; nt < 4; nt++)
#pragma unroll
                    for (int i = 0; i < 4; i++) acc[mt][nt][i] = 0.f;

            const uint32_t* src = isH1 ? hsfA : hsfB;
#pragma unroll
            for (int ktl = 0; ktl < 8; ktl++) {
                int kt = wq * 8 + ktl;
#pragma unroll
                for (int mt = 0; mt < 4; mt++) {
                    uint4 av = *(const uint4*)&src[(((mt * 32 + kt) * 32) + lane) * 4];
                    uint32_t a[4] = {av.x, av.y, av.z, av.w};
#pragma unroll
                    for (int nt = 0; nt < 4; nt++)
                        mma_f16(acc[mt][nt], a, bfr[nt][ktl]);
                }
            }

#pragma unroll
            for (int mt = 0; mt < 4; mt++)
#pragma unroll
                for (int nt = 0; nt < 4; nt++)
                    *(float4*)&red[(((w * 4 + mt) * 4 + nt) << 7) + lane * 4] =
                        make_float4(acc[mt][nt][0], acc[mt][nt][1],
                                    acc[mt][nt][2], acc[mt][nt][3]);
            __syncthreads();

            __half* ring = g_h2f[s & 1];
#pragma unroll
            for (int half = 0; half < 2; half++) {
                int b     = bq + half * 32;
                int row_t = b & 15;
                int mt    = b >> 4;
                int pos   = (((row_t & 7) * 4 + (jj >> 1)) << 2) + (jj & 1) +
                            ((row_t >> 3) << 1);
                float gv[4];
#pragma unroll
                for (int g = 0; g < 4; g++) {
                    float sacc = bs[g];
#pragma unroll
                    for (int ww = 0; ww < 8; ww++)
                        sacc += red[(((ww * 4 + mt) * 4 + g) << 7) + pos];
                    gv[g] = sacc;
                }
                float ig = 1.f / (1.f + __expf(-gv[0]));
                float fg = 1.f / (1.f + __expf(-gv[1]));
                float gg = tanhf(gv[2]);
                float og = 1.f / (1.f + __expf(-gv[3]));
                float cold = half ? creg1 : creg0;
                float cn = fg * cold + ig * gg;
                if (half) creg1 = cn; else creg0 = cn;
                float hn = og * tanhf(cn);
                __half hb = __float2half_rn(hn);
                st_hfrag(ring, b, j0 + jj, hb);
                hseq[(size_t)(b * T_ + s) * H_ + j0 + jj] = hb;
            }

            __syncthreads();
            if (tid == 0) st_rel(&g_flags2[bid2 * 4], (unsigned)(s + 1));
        }
    }

    // ===================== FC worker pool (round-10 verbatim) ==============
    {
        uint8_t* dsm = (uint8_t*)smu;
        const uint32_t base = smem_u32(dsm);
        const int wm = (w & 1) * 64;
        const int wn = (w >> 1) * 64;

        while (true) {
            __syncthreads();
            if (tid == 0) s_w = atomicAdd(&g_ticket, 1);
            __syncthreads();
            int tw = s_w;
            if (tw >= NFCT) break;

            int g  = tw / 500;
            int u  = tw % 500;
            int b0 = (u / 125) * 16;
            int n0 = (u % 125) * 256;
            int t0 = g * 8;

            if (tid < 64) {
                unsigned need = (unsigned)(8 * (g + 1));
                while (ld_acq(&g_flags2[tid * 4]) < need) __nanosleep(128);
            }
            __syncthreads();

            float acc[4][8][4];
#pragma unroll
            for (int mt = 0; mt < 4; mt++)
#pragma unroll
                for (int nt = 0; nt < 8; nt++)
#pragma unroll
                    for (int i = 0; i < 4; i++) acc[mt][nt][i] = 0.f;

            auto issue = [&](int s) {
                uint32_t sa = base + (s & 3) * FSTG;
                uint32_t sb = sa + 128 * HLDW * 4;
#pragma unroll
                for (int i = 0; i < 2; i++) {
                    int c = i * 256 + tid;
                    int row = c >> 2, kk = c & 3;
                    int m = (b0 + (row >> 3)) * T_ + t0 + (row & 7);
                    cp16(sa + (uint32_t)(row * 80 + kk * 16),
                         hseq + (size_t)m * H_ + s * 32 + kk * 8);
                }
#pragma unroll
                for (int i = 0; i < 4; i++) {
                    int c = i * 256 + tid;
                    int row = c >> 2, kk = c & 3;
                    cp16(sb + (uint32_t)(row * 80 + kk * 16),
                         fcw + (size_t)(n0 + row) * H_ + s * 32 + kk * 8);
                }
            };

#pragma unroll
            for (int s = 0; s < 3; s++) {
                issue(s);
                asm volatile("cp.async.commit_group;" ::: "memory");
            }

            for (int k = 0; k < 16; k++) {
                if (k <= 13)      asm volatile("cp.async.wait_group 2;" ::: "memory");
                else if (k == 14) asm volatile("cp.async.wait_group 1;" ::: "memory");
                else              asm volatile("cp.async.wait_group 0;" ::: "memory");
                __syncthreads();
                if (k + 3 < 16) {
                    issue(k + 3);
                    asm volatile("cp.async.commit_group;" ::: "memory");
                }

                const uint32_t* As = (const uint32_t*)(dsm + (size_t)(k & 3) * FSTG);
                const uint32_t* Bs = As + 128 * HLDW;
#pragma unroll
                for (int ks = 0; ks < 2; ks++) {
                    int kc = ks * 8 + (lane & 3);
                    uint32_t bf[8][2];
#pragma unroll
                    for (int nt = 0; nt < 8; nt++) {
                        int nr = wn + nt * 8 + (lane >> 2);
                        bf[nt][0] = Bs[nr * HLDW + kc];
                        bf[nt][1] = Bs[nr * HLDW + kc + 4];
                    }
#pragma unroll
                    for (int mt = 0; mt < 4; mt++) {
                        int r = wm + mt * 16 + (lane >> 2);
                        uint32_t af[4];
                        af[0] = As[r * HLDW + kc];
                        af[1] = As[(r + 8) * HLDW + kc];
                        af[2] = As[r * HLDW + kc + 4];
                        af[3] = As[(r + 8) * HLDW + kc + 4];
#pragma unroll
                        for (int nt = 0; nt < 8; nt++)
                            mma_f16(acc[mt][nt], af, bf[nt]);
                    }
                }
            }

#pragma unroll
            for (int nt = 0; nt < 8; nt++) {
                int cn  = n0 + wn + nt * 8 + (lane & 3) * 2;
                float bv0 = fcb[cn];
                float bv1 = fcb[cn + 1];
#pragma unroll
                for (int mt = 0; mt < 4; mt++) {
                    int r  = wm + mt * 16 + (lane >> 2);
                    int b1 = b0 + (r >> 3),       t1 = t0 + (r & 7);
                    int b2 = b0 + ((r + 8) >> 3), t2 = t0 + ((r + 8) & 7);
                    size_t base1 = (size_t)b1 * V_ * T_ + t1;
                    size_t base2 = (size_t)b2 * V_ * T_ + t2;
                    out[base1 + (size_t)cn * T_]       = acc[mt][nt][0] + bv0;
                    out[base1 + (size_t)(cn + 1) * T_] = acc[mt][nt][1] + bv1;
                    out[base2 + (size_t)cn * T_]       = acc[mt][nt][2] + bv0;
                    out[base2 + (size_t)(cn + 1) * T_] = acc[mt][nt][3] + bv1;
                }
            }
        }
    }
}

// ---------------------------------------------------------------------------
extern "C" void kernel_launch(void* const* d_in, const int* in_sizes, int n_in,
                              void* d_out, int out_size) {
    (void)in_sizes; (void)n_in; (void)out_size;
    const int*   sentence = (const int*)d_in[0];
    const float* features = (const float*)d_in[1];
    const float* emb   = (const float*)d_in[3];
    const float* W_ih0 = (const float*)d_in[4];
    const float* W_hh0 = (const float*)d_in[5];
    const float* b_ih0 = (const float*)d_in[6];
    const float* b_hh0 = (const float*)d_in[7];
    const float* W_ih1 = (const float*)d_in[8];
    const float* W_hh1 = (const float*)d_in[9];
    const float* b_ih1 = (const float*)d_in[10];
    const float* b_hh1 = (const float*)d_in[11];
    const float* fc_W  = (const float*)d_in[12];
    const float* fc_b  = (const float*)d_in[13];
    float* out = (float*)d_out;

    float *xp;
    __half *x0, *hseq, *wih0, *wih1, *fcw;
    cudaGetSymbolAddress((void**)&x0, g_x0);
    cudaGetSymbolAddress((void**)&xp, g_xp);
    cudaGetSymbolAddress((void**)&hseq, g_hseq);
    cudaGetSymbolAddress((void**)&wih0, g_wih0);
    cudaGetSymbolAddress((void**)&wih1, g_wih1);
    cudaGetSymbolAddress((void**)&fcw, g_fcw);

    cudaFuncSetAttribute(wave_fc,
                         cudaFuncAttributeMaxDynamicSharedMemorySize, 196608);
    cudaFuncSetAttribute(gemm_proj,
                         cudaFuncAttributeMaxDynamicSharedMemorySize, 4 * GSTG);

    to_half<<<(G4_ * E_ / 4 + 255) / 256, 256>>>(W_ih0, wih0, G4_ * E_ / 4);
    to_half<<<(G4_ * H_ / 4 + 255) / 256, 256>>>(W_ih1, wih1, G4_ * H_ / 4);
    to_half<<<(V_ * H_ / 4 + 255) / 256, 256>>>(fc_W, fcw, V_ * H_ / 4);

    build_x0<<<(M_ * (E_ / 4) + 255) / 256, 256>>>(sentence, features, emb, x0);

    gemm_proj<<<dim3(G4_ / 256, M_ / 128), 256, 4 * GSTG>>>(
        x0, wih0, b_ih0, b_hh0, xp, M_, G4_, E_);

    reset_bar<<<1, 256>>>();
    wave_fc<<<148, 256, 196608>>>(xp, W_hh0, wih1, W_hh1, b_ih1, b_hh1,
                                  hseq, fcw, fc_b, out);
}

// round 15
// speedup vs baseline: 1.1791x; 1.1791x over previous
#include <cuda_runtime.h>
#include <cuda_fp16.h>
#include <cstdint>

// ---------------------------------------------------------------------------
// Decoder: emb gather + concat -> fused [wavefront LSTM x2 + FC drain]
// B=64, T=32, E=H=512, V=32000.
// Round-10 base VERBATIM (best measured: 499.7us), with exactly ONE change:
// the layer-0 projection GEMM uses the R7/R8-proven BN=256 8-warp config.
// ---------------------------------------------------------------------------
#define B_  64
#define T_  32
#define E_  512
#define H_  512
#define V_  32000
#define M_  (B_ * T_)    // 2048
#define G4_ (4 * H_)     // 2048
#define NFCT 2000        // FC tiles: 4 tgroups x 4 btiles x 125 ntiles

__device__ __half   g_x0[M_ * E_];
__device__ float    g_xp[M_ * G4_];
__device__ __half   g_hseq[M_ * H_];
__device__ __half   g_wih0[G4_ * E_];
__device__ __half   g_wih1[G4_ * H_];
__device__ __half   g_fcw[V_ * H_];
__device__ __align__(16) __half g_h1ring[4][B_ * H_];
__device__ __align__(16) __half g_h2f[2][B_ * H_];
__device__ unsigned g_flags1[64 * 4];
__device__ unsigned g_flags2[64 * 4];
__device__ unsigned g_ticket;

// ---------------------------------------------------------------------------
__device__ __forceinline__ uint32_t packh2(float a, float b) {
    __half2 h = __floats2half2_rn(a, b);
    return *(uint32_t*)&h;
}

__device__ __forceinline__ void mma_f16(float (&c)[4], const uint32_t (&a)[4],
                                        const uint32_t (&b)[2]) {
    asm volatile(
        "mma.sync.aligned.m16n8k16.row.col.f32.f16.f16.f32 "
        "{%0,%1,%2,%3}, {%4,%5,%6,%7}, {%8,%9}, {%0,%1,%2,%3};\n"
        : "+f"(c[0]), "+f"(c[1]), "+f"(c[2]), "+f"(c[3])
        : "r"(a[0]), "r"(a[1]), "r"(a[2]), "r"(a[3]), "r"(b[0]), "r"(b[1]));
}

__device__ __forceinline__ void st_rel(unsigned* p, unsigned v) {
    asm volatile("st.release.gpu.global.u32 [%0], %1;" :: "l"(p), "r"(v)
                 : "memory");
}
__device__ __forceinline__ unsigned ld_acq(unsigned* p) {
    unsigned v;
    asm volatile("ld.acquire.gpu.global.u32 %0, [%1];" : "=r"(v) : "l"(p)
                 : "memory");
    return v;
}

__device__ __forceinline__ uint32_t smem_u32(const void* p) {
    uint32_t a;
    asm("{ .reg .u64 t; cvta.to.shared.u64 t, %1; cvt.u32.u64 %0, t; }"
        : "=r"(a) : "l"(p));
    return a;
}

__device__ __forceinline__ void cp16(uint32_t dst, const void* src) {
    asm volatile("cp.async.cg.shared.global [%0], [%1], 16;\n"
                 :: "r"(dst), "l"(src));
}

// m16n8k16 A-fragment-layout store (h ring buffers)
__device__ __forceinline__ void st_hfrag(__half* base, int b, int j, __half h) {
    int mt     = b >> 4;
    int kt     = j >> 4;
    int lane_t = (b & 7) * 4 + ((j >> 1) & 3);
    int q      = ((b >> 3) & 1) | (((j >> 3) & 1) << 1);
    base[(((mt * 32 + kt) * 32 + lane_t) << 3) + (q << 1) + (j & 1)] = h;
}

// ---------------------------------------------------------------------------
__global__ void to_half(const float* __restrict__ src, __half* __restrict__ dst,
                        int n4) {
    int i = blockIdx.x * blockDim.x + threadIdx.x;
    if (i >= n4) return;
    float4 v = *(const float4*)(src + (size_t)i * 4);
    uint2 u;
    u.x = packh2(v.x, v.y);
    u.y = packh2(v.z, v.w);
    *(uint2*)(dst + (size_t)i * 4) = u;
}

__global__ void build_x0(const int* __restrict__ sentence,
                         const float* __restrict__ features,
                         const float* __restrict__ emb,
                         __half* __restrict__ x0) {
    int i4 = blockIdx.x * blockDim.x + threadIdx.x;
    if (i4 >= M_ * (E_ / 4)) return;
    int m  = i4 >> 7;
    int e4 = (i4 & 127) * 4;
    int b  = m >> 5;
    int t  = m & 31;
    float4 v;
    if (t == 0) {
        v = *(const float4*)&features[b * E_ + e4];
    } else {
        int tok = sentence[b * T_ + (t - 1)];
        v = *(const float4*)&emb[tok * E_ + e4];
    }
    uint2 u;
    u.x = packh2(v.x, v.y);
    u.y = packh2(v.z, v.w);
    *(uint2*)(x0 + (size_t)m * E_ + e4) = u;
}

__global__ void reset_bar() {
    int i = threadIdx.x;
    if (i < 256) { g_flags1[i] = 0; g_flags2[i] = 0; }
    if (i == 0) g_ticket = 0;
}

// ---------------------------------------------------------------------------
// Projection GEMM (R7/R8-proven): BM=128 BN=256 BK=32, 4-stage cp.async,
// 8 warps (2m x 4n), warp tile 64x64, K=512, row-major C + bias1 + bias2.
// ---------------------------------------------------------------------------
#define HLDW 20
#define GSTG ((128 + 256) * HLDW * 4)   // 30720 B/stage

__global__ void __launch_bounds__(256)
gemm_proj(const __half* __restrict__ A, const __half* __restrict__ Bm,
          const float* __restrict__ bias1, const float* __restrict__ bias2,
          float* __restrict__ C, int M, int N, int K) {
    extern __shared__ uint8_t dsm[];
    const uint32_t base = smem_u32(dsm);

    const int tid  = threadIdx.x;
    const int lane = tid & 31;
    const int warp = tid >> 5;
    const int wm = (warp & 1) * 64;
    const int wn = (warp >> 1) * 64;
    const int m0 = blockIdx.y * 128;
    const int n0 = blockIdx.x * 256;

    float acc[4][8][4];
#pragma unroll
    for (int mt = 0; mt < 4; mt++)
#pragma unroll
        for (int nt = 0; nt < 8; nt++)
#pragma unroll
            for (int i = 0; i < 4; i++) acc[mt][nt][i] = 0.f;

    auto issue = [&](int s) {
        uint32_t sa = base + (s & 3) * GSTG;
        uint32_t sb = sa + 128 * HLDW * 4;
        const __half* ap = A + (size_t)m0 * K + s * 32;
        const __half* wp = Bm + (size_t)n0 * K + s * 32;
#pragma unroll
        for (int i = 0; i < 2; i++) {
            int c = i * 256 + tid;
            int row = c >> 2, kk = c & 3;
            cp16(sa + (uint32_t)(row * 80 + kk * 16),
                 ap + (size_t)row * K + kk * 8);
        }
#pragma unroll
        for (int i = 0; i < 4; i++) {
            int c = i * 256 + tid;
            int row = c >> 2, kk = c & 3;
            cp16(sb + (uint32_t)(row * 80 + kk * 16),
                 wp + (size_t)row * K + kk * 8);
        }
    };

#pragma unroll
    for (int s = 0; s < 3; s++) {
        issue(s);
        asm volatile("cp.async.commit_group;" ::: "memory");
    }

    for (int k = 0; k < 16; k++) {
        if (k <= 13)      asm volatile("cp.async.wait_group 2;" ::: "memory");
        else if (k == 14) asm volatile("cp.async.wait_group 1;" ::: "memory");
        else              asm volatile("cp.async.wait_group 0;" ::: "memory");
        __syncthreads();
        if (k + 3 < 16) {
            issue(k + 3);
            asm volatile("cp.async.commit_group;" ::: "memory");
        }

        const uint32_t* As = (const uint32_t*)(dsm + (size_t)(k & 3) * GSTG);
        const uint32_t* Bs = As + 128 * HLDW;
#pragma unroll
        for (int ks = 0; ks < 2; ks++) {
            int kc = ks * 8 + (lane & 3);
            uint32_t bf[8][2];
#pragma unroll
            for (int nt = 0; nt < 8; nt++) {
                int nr = wn + nt * 8 + (lane >> 2);
                bf[nt][0] = Bs[nr * HLDW + kc];
                bf[nt][1] = Bs[nr * HLDW + kc + 4];
            }
#pragma unroll
            for (int mt = 0; mt < 4; mt++) {
                int r = wm + mt * 16 + (lane >> 2);
                uint32_t af[4];
                af[0] = As[r * HLDW + kc];
                af[1] = As[(r + 8) * HLDW + kc];
                af[2] = As[r * HLDW + kc + 4];
                af[3] = As[(r + 8) * HLDW + kc + 4];
#pragma unroll
                for (int nt = 0; nt < 8; nt++)
                    mma_f16(acc[mt][nt], af, bf[nt]);
            }
        }
    }

#pragma unroll
    for (int nt = 0; nt < 8; nt++) {
        int cn  = n0 + wn + nt * 8 + (lane & 3) * 2;
        float bv0 = bias1[cn] + bias2[cn];
        float bv1 = bias1[cn + 1] + bias2[cn + 1];
#pragma unroll
        for (int mt = 0; mt < 4; mt++) {
            int r = m0 + wm + mt * 16 + (lane >> 2);
            C[(size_t)r * N + cn]           = acc[mt][nt][0] + bv0;
            C[(size_t)r * N + cn + 1]       = acc[mt][nt][1] + bv1;
            C[(size_t)(r + 8) * N + cn]     = acc[mt][nt][2] + bv0;
            C[(size_t)(r + 8) * N + cn + 1] = acc[mt][nt][3] + bv1;
        }
    }
}

// ---------------------------------------------------------------------------
// Fused wave + FC kernel (ROUND-10 VERBATIM). Grid 148 x 256, 192KB smem.
// Blocks 0-63: LSTM layer 1. Blocks 64-127: LSTM layer 2 (fused input proj).
// Blocks 128-147: FC workers from launch. Wave blocks join FC pool after T_.
// FC tile: M=128 (16b x 8t), N=256, K=512; 4-stage cp.async; warp 64x64.
// ---------------------------------------------------------------------------
#define FSTG ((128 + 256) * HLDW * 4)   // 30720 B/stage, x4 = 122880

__global__ void __launch_bounds__(256, 1)
wave_fc(const float* __restrict__ xp0, const float* __restrict__ Whh0,
        const __half* __restrict__ wih1, const float* __restrict__ Whh1,
        const float* __restrict__ bih1, const float* __restrict__ bhh1,
        __half* __restrict__ hseq,
        const __half* __restrict__ fcw, const float* __restrict__ fcb,
        float* __restrict__ out) {
    extern __shared__ uint32_t smu[];
    __shared__ int s_w;
    const int tid  = threadIdx.x;
    const int lane = tid & 31;
    const int w    = tid >> 5;
    const int gid  = lane >> 2;
    const int tig  = lane & 3;
    const int jj   = tid & 7;
    const int bq   = tid >> 3;
    float creg0 = 0.f, creg1 = 0.f;

    if (blockIdx.x < 64) {
        // ================= layer 1 =================
        uint32_t* hsf = smu;
        float*    red = (float*)(smu + 16384);
        const int j0 = blockIdx.x * 8;

        uint32_t bfr[4][4][2];
#pragma unroll
        for (int nt = 0; nt < 4; nt++)
#pragma unroll
            for (int ktl = 0; ktl < 4; ktl++) {
                int n  = nt * H_ + j0 + gid;
                int kb = w * 64 + ktl * 16 + tig * 2;
                const float* wr = Whh0 + (size_t)n * H_;
                bfr[nt][ktl][0] = packh2(wr[kb],     wr[kb + 1]);
                bfr[nt][ktl][1] = packh2(wr[kb + 8], wr[kb + 9]);
            }

#pragma unroll 4
        for (int i = tid; i < 4096; i += 256)
            ((uint4*)hsf)[i] = make_uint4(0u, 0u, 0u, 0u);

        for (int t = 0; t < T_; t++) {
            float xpr[2][4];
#pragma unroll
            for (int half = 0; half < 2; half++) {
                int b = bq + half * 32;
#pragma unroll
                for (int g = 0; g < 4; g++)
                    xpr[half][g] =
                        xp0[(size_t)(b * T_ + t) * G4_ + g * H_ + j0 + jj];
            }

            if (t > 0) {
                if (tid < 64) {
                    while (ld_acq(&g_flags1[tid * 4]) < (unsigned)t)
                        __nanosleep(64);
                } else if (tid < 128 && t >= 4) {
                    while (ld_acq(&g_flags2[(tid - 64) * 4]) < (unsigned)(t - 3))
                        __nanosleep(64);
                }
                __syncthreads();
                const uint4* src = (const uint4*)g_h1ring[(t - 1) & 3];
#pragma unroll
                for (int it = 0; it < 16; it++) {
                    int idx = it * 256 + tid;
                    ((uint4*)hsf)[idx] = __ldcg(src + idx);
                }
            }
            __syncthreads();

            float acc[4][4][4];
#pragma unroll
            for (int mt = 0; mt < 4; mt++)
#pragma unroll
                for (int nt = 0; nt < 4; nt++)
#pragma unroll
                    for (int i = 0; i < 4; i++) acc[mt][nt][i] = 0.f;

#pragma unroll
            for (int ktl = 0; ktl < 4; ktl++) {
                int kt = w * 4 + ktl;
#pragma unroll
                for (int mt = 0; mt < 4; mt++) {
                    uint4 av = *(const uint4*)&hsf[(((mt * 32 + kt) * 32) + lane) * 4];
                    uint32_t a[4] = {av.x, av.y, av.z, av.w};
#pragma unroll
                    for (int nt = 0; nt < 4; nt++)
                        mma_f16(acc[mt][nt], a, bfr[nt][ktl]);
                }
            }

#pragma unroll
            for (int mt = 0; mt < 4; mt++)
#pragma unroll
                for (int nt = 0; nt < 4; nt++)
                    *(float4*)&red[(((w * 4 + mt) * 4 + nt) << 7) + lane * 4] =
                        make_float4(acc[mt][nt][0], acc[mt][nt][1],
                                    acc[mt][nt][2], acc[mt][nt][3]);
            __syncthreads();

            __half* ring = g_h1ring[t & 3];
#pragma unroll
            for (int half = 0; half < 2; half++) {
                int b     = bq + half * 32;
                int row_t = b & 15;
                int mt    = b >> 4;
                int pos   = (((row_t & 7) * 4 + (jj >> 1)) << 2) + (jj & 1) +
                            ((row_t >> 3) << 1);
                float gv[4];
#pragma unroll
                for (int g = 0; g < 4; g++) {
                    float s = xpr[half][g];
#pragma unroll
                    for (int ww = 0; ww < 8; ww++)
                        s += red[(((ww * 4 + mt) * 4 + g) << 7) + pos];
                    gv[g] = s;
                }
                float ig = 1.f / (1.f + __expf(-gv[0]));
                float fg = 1.f / (1.f + __expf(-gv[1]));
                float gg = tanhf(gv[2]);
                float og = 1.f / (1.f + __expf(-gv[3]));
                float cold = half ? creg1 : creg0;
                float cn = fg * cold + ig * gg;
                if (half) creg1 = cn; else creg0 = cn;
                float hn = og * tanhf(cn);
                st_hfrag(ring, b, j0 + jj, __float2half_rn(hn));
            }

            __syncthreads();
            if (tid == 0) st_rel(&g_flags1[blockIdx.x * 4], (unsigned)(t + 1));
        }
    } else if (blockIdx.x < 128) {
        // ================= layer 2 (fused input projection) =================
        uint32_t* hsfA = smu;
        uint32_t* hsfB = smu + 16384;
        float*    red  = (float*)(smu + 32768);
        const int bid2 = blockIdx.x - 64;
        const int j0 = bid2 * 8;
        const int wq = w & 3;
        const bool isH1 = (w < 4);

        uint32_t bfr[4][8][2];
#pragma unroll
        for (int nt = 0; nt < 4; nt++)
#pragma unroll
            for (int ktl = 0; ktl < 8; ktl++) {
                int n  = nt * H_ + j0 + gid;
                int kb = wq * 128 + ktl * 16 + tig * 2;
                if (isH1) {
                    bfr[nt][ktl][0] = *(const uint32_t*)&wih1[(size_t)n * H_ + kb];
                    bfr[nt][ktl][1] = *(const uint32_t*)&wih1[(size_t)n * H_ + kb + 8];
                } else {
                    const float* wr = Whh1 + (size_t)n * H_;
                    bfr[nt][ktl][0] = packh2(wr[kb],     wr[kb + 1]);
                    bfr[nt][ktl][1] = packh2(wr[kb + 8], wr[kb + 9]);
                }
            }

        float bs[4];
#pragma unroll
        for (int g = 0; g < 4; g++)
            bs[g] = bih1[g * H_ + j0 + jj] + bhh1[g * H_ + j0 + jj];

#pragma unroll 4
        for (int i = tid; i < 4096; i += 256)
            ((uint4*)hsfB)[i] = make_uint4(0u, 0u, 0u, 0u);

        for (int s = 0; s < T_; s++) {
            if (tid < 64) {
                while (ld_acq(&g_flags1[tid * 4]) < (unsigned)(s + 1))
                    __nanosleep(64);
            } else if (tid < 128 && s > 0) {
                while (ld_acq(&g_flags2[(tid - 64) * 4]) < (unsigned)s)
                    __nanosleep(64);
            }
            __syncthreads();
            {
                const uint4* srcA = (const uint4*)g_h1ring[s & 3];
#pragma unroll
                for (int it = 0; it < 16; it++) {
                    int idx = it * 256 + tid;
                    ((uint4*)hsfA)[idx] = __ldcg(srcA + idx);
                }
                if (s > 0) {
                    const uint4* srcB = (const uint4*)g_h2f[(s - 1) & 1];
#pragma unroll
                    for (int it = 0; it < 16; it++) {
                        int idx = it * 256 + tid;
                        ((uint4*)hsfB)[idx] = __ldcg(srcB + idx);
                    }
                }
            }
            __syncthreads();

            float acc[4][4][4];
#pragma unroll
            for (int mt = 0; mt < 4; mt++)
#pragma unroll
                for (int nt = 0; nt < 4; nt++)
#pragma unroll
                    for (int i = 0; i < 4; i++) acc[mt][nt][i] = 0.f;

            const uint32_t* src = isH1 ? hsfA : hsfB;
#pragma unroll
            for (int ktl = 0; ktl < 8; ktl++) {
                int kt = wq * 8 + ktl;
#pragma unroll
                for (int mt = 0; mt < 4; mt++) {
                    uint4 av = *(const uint4*)&src[(((mt * 32 + kt) * 32) + lane) * 4];
                    uint32_t a[4] = {av.x, av.y, av.z, av.w};
#pragma unroll
                    for (int nt = 0; nt < 4; nt++)
                        mma_f16(acc[mt][nt], a, bfr[nt][ktl]);
                }
            }

#pragma unroll
            for (int mt = 0; mt < 4; mt++)
#pragma unroll
                for (int nt = 0; nt < 4; nt++)
                    *(float4*)&red[(((w * 4 + mt) * 4 + nt) << 7) + lane * 4] =
                        make_float4(acc[mt][nt][0], acc[mt][nt][1],
                                    acc[mt][nt][2], acc[mt][nt][3]);
            __syncthreads();

            __half* ring = g_h2f[s & 1];
#pragma unroll
            for (int half = 0; half < 2; half++) {
                int b     = bq + half * 32;
                int row_t = b & 15;
                int mt    = b >> 4;
                int pos   = (((row_t & 7) * 4 + (jj >> 1)) << 2) + (jj & 1) +
                            ((row_t >> 3) << 1);
                float gv[4];
#pragma unroll
                for (int g = 0; g < 4; g++) {
                    float sacc = bs[g];
#pragma unroll
                    for (int ww = 0; ww < 8; ww++)
                        sacc += red[(((ww * 4 + mt) * 4 + g) << 7) + pos];
                    gv[g] = sacc;
                }
                float ig = 1.f / (1.f + __expf(-gv[0]));
                float fg = 1.f / (1.f + __expf(-gv[1]));
                float gg = tanhf(gv[2]);
                float og = 1.f / (1.f + __expf(-gv[3]));
                float cold = half ? creg1 : creg0;
                float cn = fg * cold + ig * gg;
                if (half) creg1 = cn; else creg0 = cn;
                float hn = og * tanhf(cn);
                __half hb = __float2half_rn(hn);
                st_hfrag(ring, b, j0 + jj, hb);
                hseq[(size_t)(b * T_ + s) * H_ + j0 + jj] = hb;
            }

            __syncthreads();
            if (tid == 0) st_rel(&g_flags2[bid2 * 4], (unsigned)(s + 1));
        }
    }

    // ===================== FC worker pool (round-10 verbatim) ==============
    {
        uint8_t* dsm = (uint8_t*)smu;
        const uint32_t base = smem_u32(dsm);
        const int wm = (w & 1) * 64;
        const int wn = (w >> 1) * 64;

        while (true) {
            __syncthreads();
            if (tid == 0) s_w = atomicAdd(&g_ticket, 1);
            __syncthreads();
            int tw = s_w;
            if (tw >= NFCT) break;

            int g  = tw / 500;
            int u  = tw % 500;
            int b0 = (u / 125) * 16;
            int n0 = (u % 125) * 256;
            int t0 = g * 8;

            if (tid < 64) {
                unsigned need = (unsigned)(8 * (g + 1));
                while (ld_acq(&g_flags2[tid * 4]) < need) __nanosleep(128);
            }
            __syncthreads();

            float acc[4][8][4];
#pragma unroll
            for (int mt = 0; mt < 4; mt++)
#pragma unroll
                for (int nt = 0; nt < 8; nt++)
#pragma unroll
                    for (int i = 0; i < 4; i++) acc[mt][nt][i] = 0.f;

            auto issue = [&](int s) {
                uint32_t sa = base + (s & 3) * FSTG;
                uint32_t sb = sa + 128 * HLDW * 4;
#pragma unroll
                for (int i = 0; i < 2; i++) {
                    int c = i * 256 + tid;
                    int row = c >> 2, kk = c & 3;
                    int m = (b0 + (row >> 3)) * T_ + t0 + (row & 7);
                    cp16(sa + (uint32_t)(row * 80 + kk * 16),
                         hseq + (size_t)m * H_ + s * 32 + kk * 8);
                }
#pragma unroll
                for (int i = 0; i < 4; i++) {
                    int c = i * 256 + tid;
                    int row = c >> 2, kk = c & 3;
                    cp16(sb + (uint32_t)(row * 80 + kk * 16),
                         fcw + (size_t)(n0 + row) * H_ + s * 32 + kk * 8);
                }
            };

#pragma unroll
            for (int s = 0; s < 3; s++) {
                issue(s);
                asm volatile("cp.async.commit_group;" ::: "memory");
            }

            for (int k = 0; k < 16; k++) {
                if (k <= 13)      asm volatile("cp.async.wait_group 2;" ::: "memory");
                else if (k == 14) asm volatile("cp.async.wait_group 1;" ::: "memory");
                else              asm volatile("cp.async.wait_group 0;" ::: "memory");
                __syncthreads();
                if (k + 3 < 16) {
                    issue(k + 3);
                    asm volatile("cp.async.commit_group;" ::: "memory");
                }

                const uint32_t* As = (const uint32_t*)(dsm + (size_t)(k & 3) * FSTG);
                const uint32_t* Bs = As + 128 * HLDW;
#pragma unroll
                for (int ks = 0; ks < 2; ks++) {
                    int kc = ks * 8 + (lane & 3);
                    uint32_t bf[8][2];
#pragma unroll
                    for (int nt = 0; nt < 8; nt++) {
                        int nr = wn + nt * 8 + (lane >> 2);
                        bf[nt][0] = Bs[nr * HLDW + kc];
                        bf[nt][1] = Bs[nr * HLDW + kc + 4];
                    }
#pragma unroll
                    for (int mt = 0; mt < 4; mt++) {
                        int r = wm + mt * 16 + (lane >> 2);
                        uint32_t af[4];
                        af[0] = As[r * HLDW + kc];
                        af[1] = As[(r + 8) * HLDW + kc];
                        af[2] = As[r * HLDW + kc + 4];
                        af[3] = As[(r + 8) * HLDW + kc + 4];
#pragma unroll
                        for (int nt = 0; nt < 8; nt++)
                            mma_f16(acc[mt][nt], af, bf[nt]);
                    }
                }
            }

#pragma unroll
            for (int nt = 0; nt < 8; nt++) {
                int cn  = n0 + wn + nt * 8 + (lane & 3) * 2;
                float bv0 = fcb[cn];
                float bv1 = fcb[cn + 1];
#pragma unroll
                for (int mt = 0; mt < 4; mt++) {
                    int r  = wm + mt * 16 + (lane >> 2);
                    int b1 = b0 + (r >> 3),       t1 = t0 + (r & 7);
                    int b2 = b0 + ((r + 8) >> 3), t2 = t0 + ((r + 8) & 7);
                    size_t base1 = (size_t)b1 * V_ * T_ + t1;
                    size_t base2 = (size_t)b2 * V_ * T_ + t2;
                    out[base1 + (size_t)cn * T_]       = acc[mt][nt][0] + bv0;
                    out[base1 + (size_t)(cn + 1) * T_] = acc[mt][nt][1] + bv1;
                    out[base2 + (size_t)cn * T_]       = acc[mt][nt][2] + bv0;
                    out[base2 + (size_t)(cn + 1) * T_] = acc[mt][nt][3] + bv1;
                }
            }
        }
    }
}

// ---------------------------------------------------------------------------
extern "C" void kernel_launch(void* const* d_in, const int* in_sizes, int n_in,
                              void* d_out, int out_size) {
    (void)in_sizes; (void)n_in; (void)out_size;
    const int*   sentence = (const int*)d_in[0];
    const float* features = (const float*)d_in[1];
    const float* emb   = (const float*)d_in[3];
    const float* W_ih0 = (const float*)d_in[4];
    const float* W_hh0 = (const float*)d_in[5];
    const float* b_ih0 = (const float*)d_in[6];
    const float* b_hh0 = (const float*)d_in[7];
    const float* W_ih1 = (const float*)d_in[8];
    const float* W_hh1 = (const float*)d_in[9];
    const float* b_ih1 = (const float*)d_in[10];
    const float* b_hh1 = (const float*)d_in[11];
    const float* fc_W  = (const float*)d_in[12];
    const float* fc_b  = (const float*)d_in[13];
    float* out = (float*)d_out;

    float *xp;
    __half *x0, *hseq, *wih0, *wih1, *fcw;
    cudaGetSymbolAddress((void**)&x0, g_x0);
    cudaGetSymbolAddress((void**)&xp, g_xp);
    cudaGetSymbolAddress((void**)&hseq, g_hseq);
    cudaGetSymbolAddress((void**)&wih0, g_wih0);
    cudaGetSymbolAddress((void**)&wih1, g_wih1);
    cudaGetSymbolAddress((void**)&fcw, g_fcw);

    cudaFuncSetAttribute(wave_fc,
                         cudaFuncAttributeMaxDynamicSharedMemorySize, 196608);
    cudaFuncSetAttribute(gemm_proj,
                         cudaFuncAttributeMaxDynamicSharedMemorySize, 4 * GSTG);

    to_half<<<(G4_ * E_ / 4 + 255) / 256, 256>>>(W_ih0, wih0, G4_ * E_ / 4);
    to_half<<<(G4_ * H_ / 4 + 255) / 256, 256>>>(W_ih1, wih1, G4_ * H_ / 4);
    to_half<<<(V_ * H_ / 4 + 255) / 256, 256>>>(fc_W, fcw, V_ * H_ / 4);

    build_x0<<<(M_ * (E_ / 4) + 255) / 256, 256>>>(sentence, features, emb, x0);

    gemm_proj<<<dim3(G4_ / 256, M_ / 128), 256, 4 * GSTG>>>(
        x0, wih0, b_ih0, b_hh0, xp, M_, G4_, E_);

    reset_bar<<<1, 256>>>();
    wave_fc<<<148, 256, 196608>>>(xp, W_hh0, wih1, W_hh1, b_ih1, b_hh1,
                                  hseq, fcw, fc_b, out);
}

// round 16
// speedup vs baseline: 1.2185x; 1.0334x over previous
#include <cuda_runtime.h>
#include <cuda_fp16.h>
#include <cstdint>

// ---------------------------------------------------------------------------
// Decoder: emb gather + concat -> fused [merged-layer wavefront LSTM + FC]
// B=64, T=32, E=H=512, V=32000.
// NEW: one wave block handles BOTH layers' column slice (64 wave blocks),
// freeing 84 blocks as FC workers during the wave. Step bodies verbatim from
// the proven round-10 kernel; h1[u-1] staged once and shared by L1+L2.
// ---------------------------------------------------------------------------
#define B_  64
#define T_  32
#define E_  512
#define H_  512
#define V_  32000
#define M_  (B_ * T_)    // 2048
#define G4_ (4 * H_)     // 2048
#define NFCT 2000        // FC tiles: 4 tgroups x 4 btiles x 125 ntiles

__device__ __half   g_x0[M_ * E_];
__device__ float    g_xp[M_ * G4_];
__device__ __half   g_hseq[M_ * H_];
__device__ __half   g_wih0[G4_ * E_];
__device__ __half   g_wih1[G4_ * H_];
__device__ __half   g_fcw[V_ * H_];
__device__ __align__(16) __half g_h1ring[4][B_ * H_];
__device__ __align__(16) __half g_h2f[2][B_ * H_];
__device__ unsigned g_flags1[64 * 4];
__device__ unsigned g_flags2[64 * 4];
__device__ unsigned g_ticket;

// ---------------------------------------------------------------------------
__device__ __forceinline__ uint32_t packh2(float a, float b) {
    __half2 h = __floats2half2_rn(a, b);
    return *(uint32_t*)&h;
}

__device__ __forceinline__ void mma_f16(float (&c)[4], const uint32_t (&a)[4],
                                        const uint32_t (&b)[2]) {
    asm volatile(
        "mma.sync.aligned.m16n8k16.row.col.f32.f16.f16.f32 "
        "{%0,%1,%2,%3}, {%4,%5,%6,%7}, {%8,%9}, {%0,%1,%2,%3};\n"
        : "+f"(c[0]), "+f"(c[1]), "+f"(c[2]), "+f"(c[3])
        : "r"(a[0]), "r"(a[1]), "r"(a[2]), "r"(a[3]), "r"(b[0]), "r"(b[1]));
}

__device__ __forceinline__ void st_rel(unsigned* p, unsigned v) {
    asm volatile("st.release.gpu.global.u32 [%0], %1;" :: "l"(p), "r"(v)
                 : "memory");
}
__device__ __forceinline__ unsigned ld_acq(unsigned* p) {
    unsigned v;
    asm volatile("ld.acquire.gpu.global.u32 %0, [%1];" : "=r"(v) : "l"(p)
                 : "memory");
    return v;
}

__device__ __forceinline__ uint32_t smem_u32(const void* p) {
    uint32_t a;
    asm("{ .reg .u64 t; cvta.to.shared.u64 t, %1; cvt.u32.u64 %0, t; }"
        : "=r"(a) : "l"(p));
    return a;
}

__device__ __forceinline__ void cp16(uint32_t dst, const void* src) {
    asm volatile("cp.async.cg.shared.global [%0], [%1], 16;\n"
                 :: "r"(dst), "l"(src));
}

// m16n8k16 A-fragment-layout store (h ring buffers)
__device__ __forceinline__ void st_hfrag(__half* base, int b, int j, __half h) {
    int mt     = b >> 4;
    int kt     = j >> 4;
    int lane_t = (b & 7) * 4 + ((j >> 1) & 3);
    int q      = ((b >> 3) & 1) | (((j >> 3) & 1) << 1);
    base[(((mt * 32 + kt) * 32 + lane_t) << 3) + (q << 1) + (j & 1)] = h;
}

// ---------------------------------------------------------------------------
__global__ void to_half(const float* __restrict__ src, __half* __restrict__ dst,
                        int n4) {
    int i = blockIdx.x * blockDim.x + threadIdx.x;
    if (i >= n4) return;
    float4 v = *(const float4*)(src + (size_t)i * 4);
    uint2 u;
    u.x = packh2(v.x, v.y);
    u.y = packh2(v.z, v.w);
    *(uint2*)(dst + (size_t)i * 4) = u;
}

__global__ void build_x0(const int* __restrict__ sentence,
                         const float* __restrict__ features,
                         const float* __restrict__ emb,
                         __half* __restrict__ x0) {
    int i4 = blockIdx.x * blockDim.x + threadIdx.x;
    if (i4 >= M_ * (E_ / 4)) return;
    int m  = i4 >> 7;
    int e4 = (i4 & 127) * 4;
    int b  = m >> 5;
    int t  = m & 31;
    float4 v;
    if (t == 0) {
        v = *(const float4*)&features[b * E_ + e4];
    } else {
        int tok = sentence[b * T_ + (t - 1)];
        v = *(const float4*)&emb[tok * E_ + e4];
    }
    uint2 u;
    u.x = packh2(v.x, v.y);
    u.y = packh2(v.z, v.w);
    *(uint2*)(x0 + (size_t)m * E_ + e4) = u;
}

__global__ void reset_bar() {
    int i = threadIdx.x;
    if (i < 256) { g_flags1[i] = 0; g_flags2[i] = 0; }
    if (i == 0) g_ticket = 0;
}

// ---------------------------------------------------------------------------
// Projection GEMM (R7/R8-proven): BM=128 BN=256 BK=32, 4-stage cp.async,
// 8 warps (2m x 4n), warp tile 64x64, K=512, row-major C + bias1 + bias2.
// ---------------------------------------------------------------------------
#define HLDW 20
#define GSTG ((128 + 256) * HLDW * 4)   // 30720 B/stage

__global__ void __launch_bounds__(256)
gemm_proj(const __half* __restrict__ A, const __half* __restrict__ Bm,
          const float* __restrict__ bias1, const float* __restrict__ bias2,
          float* __restrict__ C, int M, int N, int K) {
    extern __shared__ uint8_t dsm[];
    const uint32_t base = smem_u32(dsm);

    const int tid  = threadIdx.x;
    const int lane = tid & 31;
    const int warp = tid >> 5;
    const int wm = (warp & 1) * 64;
    const int wn = (warp >> 1) * 64;
    const int m0 = blockIdx.y * 128;
    const int n0 = blockIdx.x * 256;

    float acc[4][8][4];
#pragma unroll
    for (int mt = 0; mt < 4; mt++)
#pragma unroll
        for (int nt = 0; nt < 8; nt++)
#pragma unroll
            for (int i = 0; i < 4; i++) acc[mt][nt][i] = 0.f;

    auto issue = [&](int s) {
        uint32_t sa = base + (s & 3) * GSTG;
        uint32_t sb = sa + 128 * HLDW * 4;
        const __half* ap = A + (size_t)m0 * K + s * 32;
        const __half* wp = Bm + (size_t)n0 * K + s * 32;
#pragma unroll
        for (int i = 0; i < 2; i++) {
            int c = i * 256 + tid;
            int row = c >> 2, kk = c & 3;
            cp16(sa + (uint32_t)(row * 80 + kk * 16),
                 ap + (size_t)row * K + kk * 8);
        }
#pragma unroll
        for (int i = 0; i < 4; i++) {
            int c = i * 256 + tid;
            int row = c >> 2, kk = c & 3;
            cp16(sb + (uint32_t)(row * 80 + kk * 16),
                 wp + (size_t)row * K + kk * 8);
        }
    };

#pragma unroll
    for (int s = 0; s < 3; s++) {
        issue(s);
        asm volatile("cp.async.commit_group;" ::: "memory");
    }

    for (int k = 0; k < 16; k++) {
        if (k <= 13)      asm volatile("cp.async.wait_group 2;" ::: "memory");
        else if (k == 14) asm volatile("cp.async.wait_group 1;" ::: "memory");
        else              asm volatile("cp.async.wait_group 0;" ::: "memory");
        __syncthreads();
        if (k + 3 < 16) {
            issue(k + 3);
            asm volatile("cp.async.commit_group;" ::: "memory");
        }

        const uint32_t* As = (const uint32_t*)(dsm + (size_t)(k & 3) * GSTG);
        const uint32_t* Bs = As + 128 * HLDW;
#pragma unroll
        for (int ks = 0; ks < 2; ks++) {
            int kc = ks * 8 + (lane & 3);
            uint32_t bf[8][2];
#pragma unroll
            for (int nt = 0; nt < 8; nt++) {
                int nr = wn + nt * 8 + (lane >> 2);
                bf[nt][0] = Bs[nr * HLDW + kc];
                bf[nt][1] = Bs[nr * HLDW + kc + 4];
            }
#pragma unroll
            for (int mt = 0; mt < 4; mt++) {
                int r = wm + mt * 16 + (lane >> 2);
                uint32_t af[4];
                af[0] = As[r * HLDW + kc];
                af[1] = As[(r + 8) * HLDW + kc];
                af[2] = As[r * HLDW + kc + 4];
                af[3] = As[(r + 8) * HLDW + kc + 4];
#pragma unroll
                for (int nt = 0; nt < 8; nt++)
                    mma_f16(acc[mt][nt], af, bf[nt]);
            }
        }
    }

#pragma unroll
    for (int nt = 0; nt < 8; nt++) {
        int cn  = n0 + wn + nt * 8 + (lane & 3) * 2;
        float bv0 = bias1[cn] + bias2[cn];
        float bv1 = bias1[cn + 1] + bias2[cn + 1];
#pragma unroll
        for (int mt = 0; mt < 4; mt++) {
            int r = m0 + wm + mt * 16 + (lane >> 2);
            C[(size_t)r * N + cn]           = acc[mt][nt][0] + bv0;
            C[(size_t)r * N + cn + 1]       = acc[mt][nt][1] + bv1;
            C[(size_t)(r + 8) * N + cn]     = acc[mt][nt][2] + bv0;
            C[(size_t)(r + 8) * N + cn + 1] = acc[mt][nt][3] + bv1;
        }
    }
}

// ---------------------------------------------------------------------------
// Fused merged-wave + FC kernel. Grid 148 x 256, 192KB smem.
// Blocks 0-63: BOTH LSTM layers for column slice j0=8*bid, 33 slots
//   (slot u: L1 step u [u<32], then L2 step u-1 [u>=1]).
// Blocks 64-147: FC workers from launch. Wave blocks join pool after wave.
// FC tile: M=128 (16b x 8t), N=256, K=512 (round-10 verbatim).
// ---------------------------------------------------------------------------
#define FSTG ((128 + 256) * HLDW * 4)   // 30720 B/stage, x4 = 122880

__global__ void __launch_bounds__(256, 1)
wave_fc(const float* __restrict__ xp0, const float* __restrict__ Whh0,
        const __half* __restrict__ wih1, const float* __restrict__ Whh1,
        const float* __restrict__ bih1, const float* __restrict__ bhh1,
        __half* __restrict__ hseq,
        const __half* __restrict__ fcw, const float* __restrict__ fcb,
        float* __restrict__ out) {
    extern __shared__ uint32_t smu[];
    __shared__ int s_w;
    const int tid  = threadIdx.x;
    const int lane = tid & 31;
    const int w    = tid >> 5;
    const int gid  = lane >> 2;
    const int tig  = lane & 3;
    const int jj   = tid & 7;
    const int bq   = tid >> 3;

    if (blockIdx.x < 64) {
        // ============== merged layers: slice j0 of L1 and L2 ==============
        uint32_t* hsfA = smu;                    // h1[u-1] (shared L1+L2)
        uint32_t* hsfB = smu + 16384;            // h2[u-2]
        float*    red  = (float*)(smu + 32768);
        const int j0 = blockIdx.x * 8;
        const int wq = w & 3;
        const bool isH1 = (w < 4);

        // L1 weights (W_hh0), K split 8 ways (64 K/warp)
        uint32_t bfr0[4][4][2];
#pragma unroll
        for (int nt = 0; nt < 4; nt++)
#pragma unroll
            for (int ktl = 0; ktl < 4; ktl++) {
                int n  = nt * H_ + j0 + gid;
                int kb = w * 64 + ktl * 16 + tig * 2;
                const float* wr = Whh0 + (size_t)n * H_;
                bfr0[nt][ktl][0] = packh2(wr[kb],     wr[kb + 1]);
                bfr0[nt][ktl][1] = packh2(wr[kb + 8], wr[kb + 9]);
            }
        // L2 weights: warps 0-3 W_ih1 (h1 side), warps 4-7 W_hh1 (h2 side)
        uint32_t bfr1[4][8][2];
#pragma unroll
        for (int nt = 0; nt < 4; nt++)
#pragma unroll
            for (int ktl = 0; ktl < 8; ktl++) {
                int n  = nt * H_ + j0 + gid;
                int kb = wq * 128 + ktl * 16 + tig * 2;
                if (isH1) {
                    bfr1[nt][ktl][0] = *(const uint32_t*)&wih1[(size_t)n * H_ + kb];
                    bfr1[nt][ktl][1] = *(const uint32_t*)&wih1[(size_t)n * H_ + kb + 8];
                } else {
                    const float* wr = Whh1 + (size_t)n * H_;
                    bfr1[nt][ktl][0] = packh2(wr[kb],     wr[kb + 1]);
                    bfr1[nt][ktl][1] = packh2(wr[kb + 8], wr[kb + 9]);
                }
            }

        float bs[4];
#pragma unroll
        for (int g = 0; g < 4; g++)
            bs[g] = bih1[g * H_ + j0 + jj] + bhh1[g * H_ + j0 + jj];

        // zero hsfA + hsfB (h1[-1]=0, h2[-1]=0)
#pragma unroll 4
        for (int i = tid; i < 8192; i += 256)
            ((uint4*)hsfA)[i] = make_uint4(0u, 0u, 0u, 0u);

        float c1a = 0.f, c1b = 0.f, c2a = 0.f, c2b = 0.f;

        for (int u = 0; u <= 32; u++) {
            // prefetch xp for L1 step u
            float xpr[2][4];
            if (u < 32) {
#pragma unroll
                for (int half = 0; half < 2; half++) {
                    int b = bq + half * 32;
#pragma unroll
                    for (int g = 0; g < 4; g++)
                        xpr[half][g] =
                            xp0[(size_t)(b * T_ + u) * G4_ + g * H_ + j0 + jj];
                }
            }

            if (u >= 1) {
                if (tid < 64) {
                    while (ld_acq(&g_flags1[tid * 4]) < (unsigned)u)
                        __nanosleep(64);
                } else if (tid < 128 && u >= 2) {
                    while (ld_acq(&g_flags2[(tid - 64) * 4]) < (unsigned)(u - 1))
                        __nanosleep(64);
                }
                __syncthreads();
                const uint4* srcA = (const uint4*)g_h1ring[(u - 1) & 3];
#pragma unroll
                for (int it = 0; it < 16; it++) {
                    int idx = it * 256 + tid;
                    ((uint4*)hsfA)[idx] = __ldcg(srcA + idx);
                }
                if (u >= 2) {
                    const uint4* srcB = (const uint4*)g_h2f[(u - 2) & 1];
#pragma unroll
                    for (int it = 0; it < 16; it++) {
                        int idx = it * 256 + tid;
                        ((uint4*)hsfB)[idx] = __ldcg(srcB + idx);
                    }
                }
            }
            __syncthreads();

            // ---------------- L1 step u ----------------
            if (u < 32) {
                float acc[4][4][4];
#pragma unroll
                for (int mt = 0; mt < 4; mt++)
#pragma unroll
                    for (int nt = 0; nt < 4; nt++)
#pragma unroll
                        for (int i = 0; i < 4; i++) acc[mt][nt][i] = 0.f;

#pragma unroll
                for (int ktl = 0; ktl < 4; ktl++) {
                    int kt = w * 4 + ktl;
#pragma unroll
                    for (int mt = 0; mt < 4; mt++) {
                        uint4 av = *(const uint4*)&hsfA[(((mt * 32 + kt) * 32) + lane) * 4];
                        uint32_t a[4] = {av.x, av.y, av.z, av.w};
#pragma unroll
                        for (int nt = 0; nt < 4; nt++)
                            mma_f16(acc[mt][nt], a, bfr0[nt][ktl]);
                    }
                }

#pragma unroll
                for (int mt = 0; mt < 4; mt++)
#pragma unroll
                    for (int nt = 0; nt < 4; nt++)
                        *(float4*)&red[(((w * 4 + mt) * 4 + nt) << 7) + lane * 4] =
                            make_float4(acc[mt][nt][0], acc[mt][nt][1],
                                        acc[mt][nt][2], acc[mt][nt][3]);
                __syncthreads();

                __half* ring = g_h1ring[u & 3];
#pragma unroll
                for (int half = 0; half < 2; half++) {
                    int b     = bq + half * 32;
                    int row_t = b & 15;
                    int mt    = b >> 4;
                    int pos   = (((row_t & 7) * 4 + (jj >> 1)) << 2) + (jj & 1) +
                                ((row_t >> 3) << 1);
                    float gv[4];
#pragma unroll
                    for (int g = 0; g < 4; g++) {
                        float s = xpr[half][g];
#pragma unroll
                        for (int ww = 0; ww < 8; ww++)
                            s += red[(((ww * 4 + mt) * 4 + g) << 7) + pos];
                        gv[g] = s;
                    }
                    float ig = 1.f / (1.f + __expf(-gv[0]));
                    float fg = 1.f / (1.f + __expf(-gv[1]));
                    float gg = tanhf(gv[2]);
                    float og = 1.f / (1.f + __expf(-gv[3]));
                    float cold = half ? c1b : c1a;
                    float cn = fg * cold + ig * gg;
                    if (half) c1b = cn; else c1a = cn;
                    float hn = og * tanhf(cn);
                    st_hfrag(ring, b, j0 + jj, __float2half_rn(hn));
                }

                __syncthreads();
                if (tid == 0)
                    st_rel(&g_flags1[blockIdx.x * 4], (unsigned)(u + 1));
            }

            // ---------------- L2 step u-1 ----------------
            if (u >= 1) {
                const int s = u - 1;
                float acc[4][4][4];
#pragma unroll
                for (int mt = 0; mt < 4; mt++)
#pragma unroll
                    for (int nt = 0; nt < 4; nt++)
#pragma unroll
                        for (int i = 0; i < 4; i++) acc[mt][nt][i] = 0.f;

                const uint32_t* src = isH1 ? hsfA : hsfB;
#pragma unroll
                for (int ktl = 0; ktl < 8; ktl++) {
                    int kt = wq * 8 + ktl;
#pragma unroll
                    for (int mt = 0; mt < 4; mt++) {
                        uint4 av = *(const uint4*)&src[(((mt * 32 + kt) * 32) + lane) * 4];
                        uint32_t a[4] = {av.x, av.y, av.z, av.w};
#pragma unroll
                        for (int nt = 0; nt < 4; nt++)
                            mma_f16(acc[mt][nt], a, bfr1[nt][ktl]);
                    }
                }

#pragma unroll
                for (int mt = 0; mt < 4; mt++)
#pragma unroll
                    for (int nt = 0; nt < 4; nt++)
                        *(float4*)&red[(((w * 4 + mt) * 4 + nt) << 7) + lane * 4] =
                            make_float4(acc[mt][nt][0], acc[mt][nt][1],
                                        acc[mt][nt][2], acc[mt][nt][3]);
                __syncthreads();

                __half* ring = g_h2f[s & 1];
#pragma unroll
                for (int half = 0; half < 2; half++) {
                    int b     = bq + half * 32;
                    int row_t = b & 15;
                    int mt    = b >> 4;
                    int pos   = (((row_t & 7) * 4 + (jj >> 1)) << 2) + (jj & 1) +
                                ((row_t >> 3) << 1);
                    float gv[4];
#pragma unroll
                    for (int g = 0; g < 4; g++) {
                        float sacc = bs[g];
#pragma unroll
                        for (int ww = 0; ww < 8; ww++)
                            sacc += red[(((ww * 4 + mt) * 4 + g) << 7) + pos];
                        gv[g] = sacc;
                    }
                    float ig = 1.f / (1.f + __expf(-gv[0]));
                    float fg = 1.f / (1.f + __expf(-gv[1]));
                    float gg = tanhf(gv[2]);
                    float og = 1.f / (1.f + __expf(-gv[3]));
                    float cold = half ? c2b : c2a;
                    float cn = fg * cold + ig * gg;
                    if (half) c2b = cn; else c2a = cn;
                    float hn = og * tanhf(cn);
                    __half hb = __float2half_rn(hn);
                    st_hfrag(ring, b, j0 + jj, hb);
                    hseq[(size_t)(b * T_ + s) * H_ + j0 + jj] = hb;
                }

                __syncthreads();
                if (tid == 0)
                    st_rel(&g_flags2[blockIdx.x * 4], (unsigned)(s + 1));
            }
        }
    }

    // ===================== FC worker pool (round-10 verbatim) ==============
    {
        uint8_t* dsm = (uint8_t*)smu;
        const uint32_t base = smem_u32(dsm);
        const int wm = (w & 1) * 64;
        const int wn = (w >> 1) * 64;

        while (true) {
            __syncthreads();
            if (tid == 0) s_w = atomicAdd(&g_ticket, 1);
            __syncthreads();
            int tw = s_w;
            if (tw >= NFCT) break;

            int g  = tw / 500;
            int u  = tw % 500;
            int b0 = (u / 125) * 16;
            int n0 = (u % 125) * 256;
            int t0 = g * 8;

            if (tid < 64) {
                unsigned need = (unsigned)(8 * (g + 1));
                while (ld_acq(&g_flags2[tid * 4]) < need) __nanosleep(128);
            }
            __syncthreads();

            float acc[4][8][4];
#pragma unroll
            for (int mt = 0; mt < 4; mt++)
#pragma unroll
                for (int nt = 0; nt < 8; nt++)
#pragma unroll
                    for (int i = 0; i < 4; i++) acc[mt][nt][i] = 0.f;

            auto issue = [&](int s) {
                uint32_t sa = base + (s & 3) * FSTG;
                uint32_t sb = sa + 128 * HLDW * 4;
#pragma unroll
                for (int i = 0; i < 2; i++) {
                    int c = i * 256 + tid;
                    int row = c >> 2, kk = c & 3;
                    int m = (b0 + (row >> 3)) * T_ + t0 + (row & 7);
                    cp16(sa + (uint32_t)(row * 80 + kk * 16),
                         hseq + (size_t)m * H_ + s * 32 + kk * 8);
                }
#pragma unroll
                for (int i = 0; i < 4; i++) {
                    int c = i * 256 + tid;
                    int row = c >> 2, kk = c & 3;
                    cp16(sb + (uint32_t)(row * 80 + kk * 16),
                         fcw + (size_t)(n0 + row) * H_ + s * 32 + kk * 8);
                }
            };

#pragma unroll
            for (int s = 0; s < 3; s++) {
                issue(s);
                asm volatile("cp.async.commit_group;" ::: "memory");
            }

            for (int k = 0; k < 16; k++) {
                if (k <= 13)      asm volatile("cp.async.wait_group 2;" ::: "memory");
                else if (k == 14) asm volatile("cp.async.wait_group 1;" ::: "memory");
                else              asm volatile("cp.async.wait_group 0;" ::: "memory");
                __syncthreads();
                if (k + 3 < 16) {
                    issue(k + 3);
                    asm volatile("cp.async.commit_group;" ::: "memory");
                }

                const uint32_t* As = (const uint32_t*)(dsm + (size_t)(k & 3) * FSTG);
                const uint32_t* Bs = As + 128 * HLDW;
#pragma unroll
                for (int ks = 0; ks < 2; ks++) {
                    int kc = ks * 8 + (lane & 3);
                    uint32_t bf[8][2];
#pragma unroll
                    for (int nt = 0; nt < 8; nt++) {
                        int nr = wn + nt * 8 + (lane >> 2);
                        bf[nt][0] = Bs[nr * HLDW + kc];
                        bf[nt][1] = Bs[nr * HLDW + kc + 4];
                    }
#pragma unroll
                    for (int mt = 0; mt < 4; mt++) {
                        int r = wm + mt * 16 + (lane >> 2);
                        uint32_t af[4];
                        af[0] = As[r * HLDW + kc];
                        af[1] = As[(r + 8) * HLDW + kc];
                        af[2] = As[r * HLDW + kc + 4];
                        af[3] = As[(r + 8) * HLDW + kc + 4];
#pragma unroll
                        for (int nt = 0; nt < 8; nt++)
                            mma_f16(acc[mt][nt], af, bf[nt]);
                    }
                }
            }

#pragma unroll
            for (int nt = 0; nt < 8; nt++) {
                int cn  = n0 + wn + nt * 8 + (lane & 3) * 2;
                float bv0 = fcb[cn];
                float bv1 = fcb[cn + 1];
#pragma unroll
                for (int mt = 0; mt < 4; mt++) {
                    int r  = wm + mt * 16 + (lane >> 2);
                    int b1 = b0 + (r >> 3),       t1 = t0 + (r & 7);
                    int b2 = b0 + ((r + 8) >> 3), t2 = t0 + ((r + 8) & 7);
                    size_t base1 = (size_t)b1 * V_ * T_ + t1;
                    size_t base2 = (size_t)b2 * V_ * T_ + t2;
                    out[base1 + (size_t)cn * T_]       = acc[mt][nt][0] + bv0;
                    out[base1 + (size_t)(cn + 1) * T_] = acc[mt][nt][1] + bv1;
                    out[base2 + (size_t)cn * T_]       = acc[mt][nt][2] + bv0;
                    out[base2 + (size_t)(cn + 1) * T_] = acc[mt][nt][3] + bv1;
                }
            }
        }
    }
}

// ---------------------------------------------------------------------------
extern "C" void kernel_launch(void* const* d_in, const int* in_sizes, int n_in,
                              void* d_out, int out_size) {
    (void)in_sizes; (void)n_in; (void)out_size;
    const int*   sentence = (const int*)d_in[0];
    const float* features = (const float*)d_in[1];
    const float* emb   = (const float*)d_in[3];
    const float* W_ih0 = (const float*)d_in[4];
    const float* W_hh0 = (const float*)d_in[5];
    const float* b_ih0 = (const float*)d_in[6];
    const float* b_hh0 = (const float*)d_in[7];
    const float* W_ih1 = (const float*)d_in[8];
    const float* W_hh1 = (const float*)d_in[9];
    const float* b_ih1 = (const float*)d_in[10];
    const float* b_hh1 = (const float*)d_in[11];
    const float* fc_W  = (const float*)d_in[12];
    const float* fc_b  = (const float*)d_in[13];
    float* out = (float*)d_out;

    float *xp;
    __half *x0, *hseq, *wih0, *wih1, *fcw;
    cudaGetSymbolAddress((void**)&x0, g_x0);
    cudaGetSymbolAddress((void**)&xp, g_xp);
    cudaGetSymbolAddress((void**)&hseq, g_hseq);
    cudaGetSymbolAddress((void**)&wih0, g_wih0);
    cudaGetSymbolAddress((void**)&wih1, g_wih1);
    cudaGetSymbolAddress((void**)&fcw, g_fcw);

    cudaFuncSetAttribute(wave_fc,
                         cudaFuncAttributeMaxDynamicSharedMemorySize, 196608);
    cudaFuncSetAttribute(gemm_proj,
                         cudaFuncAttributeMaxDynamicSharedMemorySize, 4 * GSTG);

    to_half<<<(G4_ * E_ / 4 + 255) / 256, 256>>>(W_ih0, wih0, G4_ * E_ / 4);
    to_half<<<(G4_ * H_ / 4 + 255) / 256, 256>>>(W_ih1, wih1, G4_ * H_ / 4);
    to_half<<<(V_ * H_ / 4 + 255) / 256, 256>>>(fc_W, fcw, V_ * H_ / 4);

    build_x0<<<(M_ * (E_ / 4) + 255) / 256, 256>>>(sentence, features, emb, x0);

    gemm_proj<<<dim3(G4_ / 256, M_ / 128), 256, 4 * GSTG>>>(
        x0, wih0, b_ih0, b_hh0, xp, M_, G4_, E_);

    reset_bar<<<1, 256>>>();
    wave_fc<<<148, 256, 196608>>>(xp, W_hh0, wih1, W_hh1, b_ih1, b_hh1,
                                  hseq, fcw, fc_b, out);
}